// round 3
// baseline (speedup 1.0000x reference)
#include <cuda_runtime.h>

#define NROWS 32768
#define CCLS  2048
#define DDIM  512

#define BM 128
#define BN 128
#define BK 16

// scratch for per-class squared norms (no cudaMalloc allowed)
__device__ float g_m2[CCLS];

// ---------------------------------------------------------------------------
// Kernel 0: m2[c] = sum_d mu[c][d]^2
// ---------------------------------------------------------------------------
__global__ void k_m2(const float* __restrict__ mu) {
    const int c = blockIdx.x;
    const float* r = mu + (size_t)c * DDIM;
    float s = 0.f;
    for (int d = threadIdx.x; d < DDIM; d += 128) {
        float v = r[d];
        s = fmaf(v, v, s);
    }
    #pragma unroll
    for (int o = 16; o; o >>= 1) s += __shfl_xor_sync(0xffffffffu, s, o);
    __shared__ float sm[4];
    if ((threadIdx.x & 31) == 0) sm[threadIdx.x >> 5] = s;
    __syncthreads();
    if (threadIdx.x == 0) g_m2[c] = sm[0] + sm[1] + sm[2] + sm[3];
}

// ---------------------------------------------------------------------------
// Kernel 1: S[i][j] = 2 * (X[i] . MU[j]) - m2[j]   (scores, row-shifted by x2)
// Classic SGEMM: 128x128 tile, BK=16, 256 threads, 8x8 per-thread, double buffer.
// ---------------------------------------------------------------------------
__global__ __launch_bounds__(256, 2)
void k_gemm(const float* __restrict__ X, const float* __restrict__ MU,
            float* __restrict__ S) {
    __shared__ float As[2][BK][BM];
    __shared__ float Bs[2][BK][BN];

    const int tid = threadIdx.x;
    const int bm = blockIdx.y * BM;
    const int bn = blockIdx.x * BN;
    const int tx = tid & 15;       // 0..15  -> column group (8 cols)
    const int ty = tid >> 4;       // 0..15  -> row group (8 rows)
    const int lr = tid >> 2;       // 0..63  loader row
    const int lc = (tid & 3) << 2; // 0,4,8,12 loader col (float4)

    const float* xp = X  + (size_t)(bm + lr) * DDIM + lc;
    const float* bp = MU + (size_t)(bn + lr) * DDIM + lc;

    float acc[8][8];
    #pragma unroll
    for (int i = 0; i < 8; i++)
        #pragma unroll
        for (int j = 0; j < 8; j++) acc[i][j] = 0.f;

    // prologue: load k-tile 0
    float4 ra0 = *(const float4*)(xp);
    float4 ra1 = *(const float4*)(xp + (size_t)64 * DDIM);
    float4 rb0 = *(const float4*)(bp);
    float4 rb1 = *(const float4*)(bp + (size_t)64 * DDIM);

    As[0][lc+0][lr]    = ra0.x; As[0][lc+1][lr]    = ra0.y;
    As[0][lc+2][lr]    = ra0.z; As[0][lc+3][lr]    = ra0.w;
    As[0][lc+0][lr+64] = ra1.x; As[0][lc+1][lr+64] = ra1.y;
    As[0][lc+2][lr+64] = ra1.z; As[0][lc+3][lr+64] = ra1.w;
    Bs[0][lc+0][lr]    = rb0.x; Bs[0][lc+1][lr]    = rb0.y;
    Bs[0][lc+2][lr]    = rb0.z; Bs[0][lc+3][lr]    = rb0.w;
    Bs[0][lc+0][lr+64] = rb1.x; Bs[0][lc+1][lr+64] = rb1.y;
    Bs[0][lc+2][lr+64] = rb1.z; Bs[0][lc+3][lr+64] = rb1.w;
    __syncthreads();

    int buf = 0;
    for (int k0 = 0; k0 < DDIM; k0 += BK) {
        const bool more = (k0 + BK) < DDIM;
        if (more) {
            const float* xn = xp + k0 + BK;
            const float* bq = bp + k0 + BK;
            ra0 = *(const float4*)(xn);
            ra1 = *(const float4*)(xn + (size_t)64 * DDIM);
            rb0 = *(const float4*)(bq);
            rb1 = *(const float4*)(bq + (size_t)64 * DDIM);
        }

        #pragma unroll
        for (int kk = 0; kk < BK; kk++) {
            float4 a0 = *(const float4*)&As[buf][kk][ty * 8];
            float4 a1 = *(const float4*)&As[buf][kk][ty * 8 + 4];
            float4 b0 = *(const float4*)&Bs[buf][kk][tx * 8];
            float4 b1 = *(const float4*)&Bs[buf][kk][tx * 8 + 4];
            float a[8] = {a0.x, a0.y, a0.z, a0.w, a1.x, a1.y, a1.z, a1.w};
            float b[8] = {b0.x, b0.y, b0.z, b0.w, b1.x, b1.y, b1.z, b1.w};
            #pragma unroll
            for (int i = 0; i < 8; i++)
                #pragma unroll
                for (int j = 0; j < 8; j++)
                    acc[i][j] = fmaf(a[i], b[j], acc[i][j]);
        }

        if (more) {
            const int nb = buf ^ 1;
            As[nb][lc+0][lr]    = ra0.x; As[nb][lc+1][lr]    = ra0.y;
            As[nb][lc+2][lr]    = ra0.z; As[nb][lc+3][lr]    = ra0.w;
            As[nb][lc+0][lr+64] = ra1.x; As[nb][lc+1][lr+64] = ra1.y;
            As[nb][lc+2][lr+64] = ra1.z; As[nb][lc+3][lr+64] = ra1.w;
            Bs[nb][lc+0][lr]    = rb0.x; Bs[nb][lc+1][lr]    = rb0.y;
            Bs[nb][lc+2][lr]    = rb0.z; Bs[nb][lc+3][lr]    = rb0.w;
            Bs[nb][lc+0][lr+64] = rb1.x; Bs[nb][lc+1][lr+64] = rb1.y;
            Bs[nb][lc+2][lr+64] = rb1.z; Bs[nb][lc+3][lr+64] = rb1.w;
            __syncthreads();
            buf = nb;
        }
    }

    // epilogue: s = 2*dot - m2[col]
    float m2c[8];
    #pragma unroll
    for (int j = 0; j < 8; j++) m2c[j] = g_m2[bn + tx * 8 + j];

    #pragma unroll
    for (int i = 0; i < 8; i++) {
        float* op = S + (size_t)(bm + ty * 8 + i) * CCLS + bn + tx * 8;
        float4 o0, o1;
        o0.x = 2.f * acc[i][0] - m2c[0];
        o0.y = 2.f * acc[i][1] - m2c[1];
        o0.z = 2.f * acc[i][2] - m2c[2];
        o0.w = 2.f * acc[i][3] - m2c[3];
        o1.x = 2.f * acc[i][4] - m2c[4];
        o1.y = 2.f * acc[i][5] - m2c[5];
        o1.z = 2.f * acc[i][6] - m2c[6];
        o1.w = 2.f * acc[i][7] - m2c[7];
        *(float4*)op       = o0;
        *(float4*)(op + 4) = o1;
    }
}

// ---------------------------------------------------------------------------
// Kernel 2: per-row masked softmax, in place on S.
// mode: 0=min, 1=max, 2=sum
// ---------------------------------------------------------------------------
__device__ __forceinline__ float block_red(float v, int mode, float* sred, int tid) {
    #pragma unroll
    for (int o = 16; o; o >>= 1) {
        float t = __shfl_xor_sync(0xffffffffu, v, o);
        v = (mode == 0) ? fminf(v, t) : (mode == 1) ? fmaxf(v, t) : (v + t);
    }
    __syncthreads();                       // protect sred from previous use
    if ((tid & 31) == 0) sred[tid >> 5] = v;
    __syncthreads();
    float r;
    if (mode == 0) {
        r = fminf(fminf(fminf(sred[0], sred[1]), fminf(sred[2], sred[3])),
                  fminf(fminf(sred[4], sred[5]), fminf(sred[6], sred[7])));
    } else if (mode == 1) {
        r = fmaxf(fmaxf(fmaxf(sred[0], sred[1]), fmaxf(sred[2], sred[3])),
                  fmaxf(fmaxf(sred[4], sred[5]), fmaxf(sred[6], sred[7])));
    } else {
        r = ((sred[0] + sred[1]) + (sred[2] + sred[3])) +
            ((sred[4] + sred[5]) + (sred[6] + sred[7]));
    }
    return r;
}

__global__ __launch_bounds__(256)
void k_softmax(float* __restrict__ S, const float* __restrict__ cK) {
    __shared__ float sred[8];
    const int row = blockIdx.x;
    const int tid = threadIdx.x;
    float4* sp = (float4*)(S + (size_t)row * CCLS);
    const float4* cp = (const float4*)cK;

    float4 v0 = sp[tid];
    float4 v1 = sp[tid + 256];
    float4 c0 = cp[tid];
    float4 c1 = cp[tid + 256];

    // 1) row min over ALL columns (pre-mask)
    float mn = fminf(fminf(fminf(v0.x, v0.y), fminf(v0.z, v0.w)),
                     fminf(fminf(v1.x, v1.y), fminf(v1.z, v1.w)));
    mn = block_red(mn, 0, sred, tid);
    const float mval = mn - 1.f;

    // 2) mask unvisited classes (cK == 0)
    v0.x = (c0.x == 0.f) ? mval : v0.x;
    v0.y = (c0.y == 0.f) ? mval : v0.y;
    v0.z = (c0.z == 0.f) ? mval : v0.z;
    v0.w = (c0.w == 0.f) ? mval : v0.w;
    v1.x = (c1.x == 0.f) ? mval : v1.x;
    v1.y = (c1.y == 0.f) ? mval : v1.y;
    v1.z = (c1.z == 0.f) ? mval : v1.z;
    v1.w = (c1.w == 0.f) ? mval : v1.w;

    // 3) row max
    float mx = fmaxf(fmaxf(fmaxf(v0.x, v0.y), fmaxf(v0.z, v0.w)),
                     fmaxf(fmaxf(v1.x, v1.y), fmaxf(v1.z, v1.w)));
    mx = block_red(mx, 1, sred, tid);

    // 4) exp + sum
    float4 e0, e1;
    e0.x = expf(v0.x - mx); e0.y = expf(v0.y - mx);
    e0.z = expf(v0.z - mx); e0.w = expf(v0.w - mx);
    e1.x = expf(v1.x - mx); e1.y = expf(v1.y - mx);
    e1.z = expf(v1.z - mx); e1.w = expf(v1.w - mx);
    float sum = ((e0.x + e0.y) + (e0.z + e0.w)) + ((e1.x + e1.y) + (e1.z + e1.w));
    sum = block_red(sum, 2, sred, tid);
    const float inv = 1.f / sum;

    // 5) normalize + write
    e0.x *= inv; e0.y *= inv; e0.z *= inv; e0.w *= inv;
    e1.x *= inv; e1.y *= inv; e1.z *= inv; e1.w *= inv;
    sp[tid]       = e0;
    sp[tid + 256] = e1;
}

// ---------------------------------------------------------------------------
extern "C" void kernel_launch(void* const* d_in, const int* in_sizes, int n_in,
                              void* d_out, int out_size) {
    const float* X  = (const float*)d_in[0];   // (N, D) fp32
    const float* MU = (const float*)d_in[1];   // (C, D) fp32
    const float* cK = (const float*)d_in[2];   // (C,)   fp32
    float* out = (float*)d_out;                // (N, C) fp32

    k_m2<<<CCLS, 128>>>(MU);

    dim3 grid(CCLS / BN, NROWS / BM);          // (16, 256)
    k_gemm<<<grid, 256>>>(X, MU, out);

    k_softmax<<<NROWS, 256>>>(out, cK);
}

// round 4
// speedup vs baseline: 1.0010x; 1.0010x over previous
#include <cuda_runtime.h>

#define NROWS 32768
#define CCLS  2048
#define DDIM  512

#define BM 128
#define BN 128
#define BK 16

// scratch for per-class squared norms (no cudaMalloc allowed)
__device__ float g_m2[CCLS];

// ---------------------------------------------------------------------------
// Kernel 0: m2[c] = sum_d mu[c][d]^2
// ---------------------------------------------------------------------------
__global__ void k_m2(const float* __restrict__ mu) {
    const int c = blockIdx.x;
    const float* r = mu + (size_t)c * DDIM;
    float s = 0.f;
    for (int d = threadIdx.x; d < DDIM; d += 128) {
        float v = r[d];
        s = fmaf(v, v, s);
    }
    #pragma unroll
    for (int o = 16; o; o >>= 1) s += __shfl_xor_sync(0xffffffffu, s, o);
    __shared__ float sm[4];
    if ((threadIdx.x & 31) == 0) sm[threadIdx.x >> 5] = s;
    __syncthreads();
    if (threadIdx.x == 0) g_m2[c] = sm[0] + sm[1] + sm[2] + sm[3];
}

// ---------------------------------------------------------------------------
// Kernel 1: S[i][j] = 2 * (X[i] . MU[j]) - m2[j]   (scores, row-shifted by x2)
// Classic SGEMM: 128x128 tile, BK=16, 256 threads, 8x8 per-thread, double buffer.
// ---------------------------------------------------------------------------
__global__ __launch_bounds__(256, 2)
void k_gemm(const float* __restrict__ X, const float* __restrict__ MU,
            float* __restrict__ S) {
    __shared__ float As[2][BK][BM];
    __shared__ float Bs[2][BK][BN];

    const int tid = threadIdx.x;
    const int bm = blockIdx.y * BM;
    const int bn = blockIdx.x * BN;
    const int tx = tid & 15;       // 0..15  -> column group (8 cols)
    const int ty = tid >> 4;       // 0..15  -> row group (8 rows)
    const int lr = tid >> 2;       // 0..63  loader row
    const int lc = (tid & 3) << 2; // 0,4,8,12 loader col (float4)

    const float* xp = X  + (size_t)(bm + lr) * DDIM + lc;
    const float* bp = MU + (size_t)(bn + lr) * DDIM + lc;

    float acc[8][8];
    #pragma unroll
    for (int i = 0; i < 8; i++)
        #pragma unroll
        for (int j = 0; j < 8; j++) acc[i][j] = 0.f;

    // prologue: load k-tile 0
    float4 ra0 = *(const float4*)(xp);
    float4 ra1 = *(const float4*)(xp + (size_t)64 * DDIM);
    float4 rb0 = *(const float4*)(bp);
    float4 rb1 = *(const float4*)(bp + (size_t)64 * DDIM);

    As[0][lc+0][lr]    = ra0.x; As[0][lc+1][lr]    = ra0.y;
    As[0][lc+2][lr]    = ra0.z; As[0][lc+3][lr]    = ra0.w;
    As[0][lc+0][lr+64] = ra1.x; As[0][lc+1][lr+64] = ra1.y;
    As[0][lc+2][lr+64] = ra1.z; As[0][lc+3][lr+64] = ra1.w;
    Bs[0][lc+0][lr]    = rb0.x; Bs[0][lc+1][lr]    = rb0.y;
    Bs[0][lc+2][lr]    = rb0.z; Bs[0][lc+3][lr]    = rb0.w;
    Bs[0][lc+0][lr+64] = rb1.x; Bs[0][lc+1][lr+64] = rb1.y;
    Bs[0][lc+2][lr+64] = rb1.z; Bs[0][lc+3][lr+64] = rb1.w;
    __syncthreads();

    int buf = 0;
    for (int k0 = 0; k0 < DDIM; k0 += BK) {
        const bool more = (k0 + BK) < DDIM;
        if (more) {
            const float* xn = xp + k0 + BK;
            const float* bq = bp + k0 + BK;
            ra0 = *(const float4*)(xn);
            ra1 = *(const float4*)(xn + (size_t)64 * DDIM);
            rb0 = *(const float4*)(bq);
            rb1 = *(const float4*)(bq + (size_t)64 * DDIM);
        }

        #pragma unroll
        for (int kk = 0; kk < BK; kk++) {
            float4 a0 = *(const float4*)&As[buf][kk][ty * 8];
            float4 a1 = *(const float4*)&As[buf][kk][ty * 8 + 4];
            float4 b0 = *(const float4*)&Bs[buf][kk][tx * 8];
            float4 b1 = *(const float4*)&Bs[buf][kk][tx * 8 + 4];
            float a[8] = {a0.x, a0.y, a0.z, a0.w, a1.x, a1.y, a1.z, a1.w};
            float b[8] = {b0.x, b0.y, b0.z, b0.w, b1.x, b1.y, b1.z, b1.w};
            #pragma unroll
            for (int i = 0; i < 8; i++)
                #pragma unroll
                for (int j = 0; j < 8; j++)
                    acc[i][j] = fmaf(a[i], b[j], acc[i][j]);
        }

        if (more) {
            const int nb = buf ^ 1;
            As[nb][lc+0][lr]    = ra0.x; As[nb][lc+1][lr]    = ra0.y;
            As[nb][lc+2][lr]    = ra0.z; As[nb][lc+3][lr]    = ra0.w;
            As[nb][lc+0][lr+64] = ra1.x; As[nb][lc+1][lr+64] = ra1.y;
            As[nb][lc+2][lr+64] = ra1.z; As[nb][lc+3][lr+64] = ra1.w;
            Bs[nb][lc+0][lr]    = rb0.x; Bs[nb][lc+1][lr]    = rb0.y;
            Bs[nb][lc+2][lr]    = rb0.z; Bs[nb][lc+3][lr]    = rb0.w;
            Bs[nb][lc+0][lr+64] = rb1.x; Bs[nb][lc+1][lr+64] = rb1.y;
            Bs[nb][lc+2][lr+64] = rb1.z; Bs[nb][lc+3][lr+64] = rb1.w;
            __syncthreads();
            buf = nb;
        }
    }

    // epilogue: s = 2*dot - m2[col]
    float m2c[8];
    #pragma unroll
    for (int j = 0; j < 8; j++) m2c[j] = g_m2[bn + tx * 8 + j];

    #pragma unroll
    for (int i = 0; i < 8; i++) {
        float* op = S + (size_t)(bm + ty * 8 + i) * CCLS + bn + tx * 8;
        float4 o0, o1;
        o0.x = 2.f * acc[i][0] - m2c[0];
        o0.y = 2.f * acc[i][1] - m2c[1];
        o0.z = 2.f * acc[i][2] - m2c[2];
        o0.w = 2.f * acc[i][3] - m2c[3];
        o1.x = 2.f * acc[i][4] - m2c[4];
        o1.y = 2.f * acc[i][5] - m2c[5];
        o1.z = 2.f * acc[i][6] - m2c[6];
        o1.w = 2.f * acc[i][7] - m2c[7];
        *(float4*)op       = o0;
        *(float4*)(op + 4) = o1;
    }
}

// ---------------------------------------------------------------------------
// Kernel 2: per-row masked softmax, in place on S.
// mode: 0=min, 1=max, 2=sum
// ---------------------------------------------------------------------------
__device__ __forceinline__ float block_red(float v, int mode, float* sred, int tid) {
    #pragma unroll
    for (int o = 16; o; o >>= 1) {
        float t = __shfl_xor_sync(0xffffffffu, v, o);
        v = (mode == 0) ? fminf(v, t) : (mode == 1) ? fmaxf(v, t) : (v + t);
    }
    __syncthreads();                       // protect sred from previous use
    if ((tid & 31) == 0) sred[tid >> 5] = v;
    __syncthreads();
    float r;
    if (mode == 0) {
        r = fminf(fminf(fminf(sred[0], sred[1]), fminf(sred[2], sred[3])),
                  fminf(fminf(sred[4], sred[5]), fminf(sred[6], sred[7])));
    } else if (mode == 1) {
        r = fmaxf(fmaxf(fmaxf(sred[0], sred[1]), fmaxf(sred[2], sred[3])),
                  fmaxf(fmaxf(sred[4], sred[5]), fmaxf(sred[6], sred[7])));
    } else {
        r = ((sred[0] + sred[1]) + (sred[2] + sred[3])) +
            ((sred[4] + sred[5]) + (sred[6] + sred[7]));
    }
    return r;
}

__global__ __launch_bounds__(256)
void k_softmax(float* __restrict__ S, const float* __restrict__ cK) {
    __shared__ float sred[8];
    const int row = blockIdx.x;
    const int tid = threadIdx.x;
    float4* sp = (float4*)(S + (size_t)row * CCLS);
    const float4* cp = (const float4*)cK;

    float4 v0 = sp[tid];
    float4 v1 = sp[tid + 256];
    float4 c0 = cp[tid];
    float4 c1 = cp[tid + 256];

    // 1) row min over ALL columns (pre-mask)
    float mn = fminf(fminf(fminf(v0.x, v0.y), fminf(v0.z, v0.w)),
                     fminf(fminf(v1.x, v1.y), fminf(v1.z, v1.w)));
    mn = block_red(mn, 0, sred, tid);
    const float mval = mn - 1.f;

    // 2) mask unvisited classes (cK == 0)
    v0.x = (c0.x == 0.f) ? mval : v0.x;
    v0.y = (c0.y == 0.f) ? mval : v0.y;
    v0.z = (c0.z == 0.f) ? mval : v0.z;
    v0.w = (c0.w == 0.f) ? mval : v0.w;
    v1.x = (c1.x == 0.f) ? mval : v1.x;
    v1.y = (c1.y == 0.f) ? mval : v1.y;
    v1.z = (c1.z == 0.f) ? mval : v1.z;
    v1.w = (c1.w == 0.f) ? mval : v1.w;

    // 3) row max
    float mx = fmaxf(fmaxf(fmaxf(v0.x, v0.y), fmaxf(v0.z, v0.w)),
                     fmaxf(fmaxf(v1.x, v1.y), fmaxf(v1.z, v1.w)));
    mx = block_red(mx, 1, sred, tid);

    // 4) exp + sum
    float4 e0, e1;
    e0.x = expf(v0.x - mx); e0.y = expf(v0.y - mx);
    e0.z = expf(v0.z - mx); e0.w = expf(v0.w - mx);
    e1.x = expf(v1.x - mx); e1.y = expf(v1.y - mx);
    e1.z = expf(v1.z - mx); e1.w = expf(v1.w - mx);
    float sum = ((e0.x + e0.y) + (e0.z + e0.w)) + ((e1.x + e1.y) + (e1.z + e1.w));
    sum = block_red(sum, 2, sred, tid);
    const float inv = 1.f / sum;

    // 5) normalize + write
    e0.x *= inv; e0.y *= inv; e0.z *= inv; e0.w *= inv;
    e1.x *= inv; e1.y *= inv; e1.z *= inv; e1.w *= inv;
    sp[tid]       = e0;
    sp[tid + 256] = e1;
}

// ---------------------------------------------------------------------------
extern "C" void kernel_launch(void* const* d_in, const int* in_sizes, int n_in,
                              void* d_out, int out_size) {
    const float* X  = (const float*)d_in[0];   // (N, D) fp32
    const float* MU = (const float*)d_in[1];   // (C, D) fp32
    const float* cK = (const float*)d_in[2];   // (C,)   fp32
    float* out = (float*)d_out;                // (N, C) fp32

    k_m2<<<CCLS, 128>>>(MU);

    dim3 grid(CCLS / BN, NROWS / BM);          // (16, 256)
    k_gemm<<<grid, 256>>>(X, MU, out);

    k_softmax<<<NROWS, 256>>>(out, cK);
}

// round 6
// speedup vs baseline: 2.6809x; 2.6782x over previous
#include <cuda_runtime.h>
#include <cuda_bf16.h>
#include <cstdint>

#define NROWS 32768
#define CCLS  2048
#define DDIM  512

// ---- GEMM tiling (mma.sync path, target-portable PTX) ----
#define BM 128
#define BN 128
#define BK 64                    // bf16 elems per chunk (128B per row)
#define KCHUNKS 24               // 3 products x (512/64)
#define TILE_BYTES 16384         // 128 rows x 128B
#define STAGE_BYTES (2 * TILE_BYTES)
#define SMEM_TOTAL  (2 * STAGE_BYTES)   // 65536

// ---- scratch (__device__ globals; no cudaMalloc allowed) ----
__device__ __nv_bfloat16 g_Ah[(size_t)NROWS * DDIM];
__device__ __nv_bfloat16 g_Al[(size_t)NROWS * DDIM];
__device__ __nv_bfloat16 g_Bh[(size_t)CCLS * DDIM];
__device__ __nv_bfloat16 g_Bl[(size_t)CCLS * DDIM];
__device__ float g_m2[CCLS];

// ===========================================================================
// PTX helpers (all supported on plain sm_103 target)
// ===========================================================================
__device__ __forceinline__ uint32_t smem_u32(const void* p) {
    uint32_t a;
    asm("{ .reg .u64 t; cvta.to.shared.u64 t, %1; cvt.u32.u64 %0, t; }" : "=r"(a) : "l"(p));
    return a;
}

__device__ __forceinline__ void cp16(uint32_t dst, const void* src) {
    asm volatile("cp.async.cg.shared.global.L2::128B [%0], [%1], 16;" :: "r"(dst), "l"(src));
}
#define CP_COMMIT() asm volatile("cp.async.commit_group;" ::: "memory")
#define CP_WAIT1()  asm volatile("cp.async.wait_group 1;" ::: "memory")

__device__ __forceinline__ void ldsm4(uint32_t* r, uint32_t addr) {
    asm volatile("ldmatrix.sync.aligned.m8n8.x4.shared.b16 {%0,%1,%2,%3}, [%4];"
                 : "=r"(r[0]), "=r"(r[1]), "=r"(r[2]), "=r"(r[3]) : "r"(addr));
}

__device__ __forceinline__ void mma16816(float* d, const uint32_t* a, const uint32_t* b) {
    asm volatile("mma.sync.aligned.m16n8k16.row.col.f32.bf16.bf16.f32 "
                 "{%0,%1,%2,%3}, {%4,%5,%6,%7}, {%8,%9}, {%0,%1,%2,%3};"
                 : "+f"(d[0]), "+f"(d[1]), "+f"(d[2]), "+f"(d[3])
                 : "r"(a[0]), "r"(a[1]), "r"(a[2]), "r"(a[3]), "r"(b[0]), "r"(b[1]));
}

// ===========================================================================
// Kernel: convert X -> bf16 hi/lo
// ===========================================================================
__global__ __launch_bounds__(256) void k_convX(const float* __restrict__ X) {
    const int idx = blockIdx.x * 256 + threadIdx.x;        // float4 index
    float4 v = ((const float4*)X)[idx];
    __nv_bfloat16 h0 = __float2bfloat16(v.x), h1 = __float2bfloat16(v.y);
    __nv_bfloat16 h2 = __float2bfloat16(v.z), h3 = __float2bfloat16(v.w);
    __nv_bfloat16 l0 = __float2bfloat16(v.x - __bfloat162float(h0));
    __nv_bfloat16 l1 = __float2bfloat16(v.y - __bfloat162float(h1));
    __nv_bfloat16 l2 = __float2bfloat16(v.z - __bfloat162float(h2));
    __nv_bfloat16 l3 = __float2bfloat16(v.w - __bfloat162float(h3));
    __nv_bfloat162* Ah = (__nv_bfloat162*)g_Ah;
    __nv_bfloat162* Al = (__nv_bfloat162*)g_Al;
    __nv_bfloat162 p;
    p.x = h0; p.y = h1; Ah[idx * 2]     = p;
    p.x = h2; p.y = h3; Ah[idx * 2 + 1] = p;
    p.x = l0; p.y = l1; Al[idx * 2]     = p;
    p.x = l2; p.y = l3; Al[idx * 2 + 1] = p;
}

// ===========================================================================
// Kernel: convert MU -> bf16 hi/lo, fused with m2[c] = ||mu_c||^2
// ===========================================================================
__global__ __launch_bounds__(128) void k_convMU(const float* __restrict__ MU) {
    const int c = blockIdx.x;
    const size_t base = (size_t)c * DDIM;
    float s = 0.f;
    #pragma unroll
    for (int j = 0; j < 4; j++) {
        int d = threadIdx.x + j * 128;
        float x = MU[base + d];
        __nv_bfloat16 h = __float2bfloat16(x);
        __nv_bfloat16 l = __float2bfloat16(x - __bfloat162float(h));
        g_Bh[base + d] = h;
        g_Bl[base + d] = l;
        s = fmaf(x, x, s);
    }
    #pragma unroll
    for (int o = 16; o; o >>= 1) s += __shfl_xor_sync(0xffffffffu, s, o);
    __shared__ float sm[4];
    if ((threadIdx.x & 31) == 0) sm[threadIdx.x >> 5] = s;
    __syncthreads();
    if (threadIdx.x == 0) g_m2[c] = sm[0] + sm[1] + sm[2] + sm[3];
}

// ===========================================================================
// Kernel: HMMA GEMM  S[i][j] = 2*(x_i . mu_j) - m2[j]
// Virtual K = 1536: phase 0 = Ah.Bh, phase 1 = Al.Bh, phase 2 = Ah.Bl
// ===========================================================================
__device__ __forceinline__ void load_chunk(uint32_t sb, int stage, int t,
                                           int bm, int bn, int tid) {
    const int phase = t >> 3;
    const int koff  = (t & 7) * BK;
    const __nv_bfloat16* A = (phase == 1) ? g_Al : g_Ah;
    const __nv_bfloat16* B = (phase == 2) ? g_Bl : g_Bh;
    const uint32_t as = sb + stage * STAGE_BYTES;
    const uint32_t bs = as + TILE_BYTES;
    #pragma unroll
    for (int i = 0; i < 4; i++) {
        int q = tid + i * 256;
        int r = q >> 3, c = q & 7;
        uint32_t off = r * 128 + ((c * 16) ^ ((r & 7) << 4));
        cp16(as + off, A + (size_t)(bm + r) * DDIM + koff + c * 8);
    }
    #pragma unroll
    for (int i = 0; i < 4; i++) {
        int q = tid + i * 256;
        int r = q >> 3, c = q & 7;
        uint32_t off = r * 128 + ((c * 16) ^ ((r & 7) << 4));
        cp16(bs + off, B + (size_t)(bn + r) * DDIM + koff + c * 8);
    }
}

__global__ __launch_bounds__(256, 2) void k_gemm_mma(float* __restrict__ S) {
    extern __shared__ char smem[];
    const uint32_t sb = smem_u32(smem);
    const int tid = threadIdx.x;
    const int wid = tid >> 5, l = tid & 31;
    const int bm = blockIdx.y * BM, bn = blockIdx.x * BN;
    const int wm = (wid & 1) * 64;      // warp row offset (64 rows)
    const int wn = (wid >> 1) * 32;     // warp col offset (32 cols)

    float acc[4][4][4];                 // [m-tile][n-tile][frag]
    #pragma unroll
    for (int i = 0; i < 4; i++)
        #pragma unroll
        for (int j = 0; j < 4; j++)
            #pragma unroll
            for (int k = 0; k < 4; k++) acc[i][j][k] = 0.f;

    // per-lane ldmatrix addressing (swizzle nibble depends only on lane)
    const uint32_t sw   = (uint32_t)(l & 7) << 4;
    const int rowA = wm + (l & 15);                       // + mt*16
    const uint32_t aColSel = ((uint32_t)(l >> 4)) << 4;   // 0 / 16 bytes
    const int rowB = wn + ((l >> 4) << 3) + (l & 7);      // + bt*16
    const uint32_t bColSel = ((uint32_t)((l >> 3) & 1)) << 4;

    // prologue
    load_chunk(sb, 0, 0, bm, bn, tid); CP_COMMIT();
    load_chunk(sb, 1, 1, bm, bn, tid); CP_COMMIT();

    for (int t = 0; t < KCHUNKS; t++) {
        CP_WAIT1();                     // chunk t resident
        __syncthreads();

        const int s = t & 1;
        const uint32_t as = sb + s * STAGE_BYTES;
        const uint32_t bs = as + TILE_BYTES;

        #pragma unroll
        for (int ks = 0; ks < 4; ks++) {
            const uint32_t kb = (uint32_t)ks * 32;
            uint32_t a[4][4], b[2][4];
            #pragma unroll
            for (int mt = 0; mt < 4; mt++)
                ldsm4(a[mt], as + (uint32_t)(rowA + mt * 16) * 128 + ((kb + aColSel) ^ sw));
            #pragma unroll
            for (int bt = 0; bt < 2; bt++)
                ldsm4(b[bt], bs + (uint32_t)(rowB + bt * 16) * 128 + ((kb + bColSel) ^ sw));
            #pragma unroll
            for (int mt = 0; mt < 4; mt++) {
                mma16816(acc[mt][0], a[mt], &b[0][0]);
                mma16816(acc[mt][1], a[mt], &b[0][2]);
                mma16816(acc[mt][2], a[mt], &b[1][0]);
                mma16816(acc[mt][3], a[mt], &b[1][2]);
            }
        }

        __syncthreads();                // all warps done reading stage s
        if (t + 2 < KCHUNKS) load_chunk(sb, s, t + 2, bm, bn, tid);
        CP_COMMIT();                    // keep group count in lockstep
    }

    // epilogue: d -> 2*d - m2[col]
    const int cbase = bn + wn + (l & 3) * 2;
    float m2v[4][2];
    #pragma unroll
    for (int nt = 0; nt < 4; nt++) {
        m2v[nt][0] = g_m2[cbase + nt * 8];
        m2v[nt][1] = g_m2[cbase + nt * 8 + 1];
    }
    const int rbase = bm + wm + (l >> 2);
    #pragma unroll
    for (int mt = 0; mt < 4; mt++) {
        #pragma unroll
        for (int nt = 0; nt < 4; nt++) {
            float2 v0, v1;
            v0.x = 2.f * acc[mt][nt][0] - m2v[nt][0];
            v0.y = 2.f * acc[mt][nt][1] - m2v[nt][1];
            v1.x = 2.f * acc[mt][nt][2] - m2v[nt][0];
            v1.y = 2.f * acc[mt][nt][3] - m2v[nt][1];
            const int r = rbase + mt * 16;
            const int c = cbase + nt * 8;
            *(float2*)(S + (size_t)r * CCLS + c)       = v0;
            *(float2*)(S + (size_t)(r + 8) * CCLS + c) = v1;
        }
    }
}

// ===========================================================================
// Kernel: per-row masked softmax, in place on S
// ===========================================================================
__device__ __forceinline__ float block_red(float v, int mode, float* sred, int tid) {
    #pragma unroll
    for (int o = 16; o; o >>= 1) {
        float t = __shfl_xor_sync(0xffffffffu, v, o);
        v = (mode == 0) ? fminf(v, t) : (mode == 1) ? fmaxf(v, t) : (v + t);
    }
    __syncthreads();
    if ((tid & 31) == 0) sred[tid >> 5] = v;
    __syncthreads();
    float r;
    if (mode == 0) {
        r = fminf(fminf(fminf(sred[0], sred[1]), fminf(sred[2], sred[3])),
                  fminf(fminf(sred[4], sred[5]), fminf(sred[6], sred[7])));
    } else if (mode == 1) {
        r = fmaxf(fmaxf(fmaxf(sred[0], sred[1]), fmaxf(sred[2], sred[3])),
                  fmaxf(fmaxf(sred[4], sred[5]), fmaxf(sred[6], sred[7])));
    } else {
        r = ((sred[0] + sred[1]) + (sred[2] + sred[3])) +
            ((sred[4] + sred[5]) + (sred[6] + sred[7]));
    }
    return r;
}

__global__ __launch_bounds__(256) void k_softmax(float* __restrict__ S,
                                                 const float* __restrict__ cK) {
    __shared__ float sred[8];
    const int row = blockIdx.x;
    const int tid = threadIdx.x;
    float4* sp = (float4*)(S + (size_t)row * CCLS);
    const float4* cp = (const float4*)cK;

    float4 v0 = sp[tid];
    float4 v1 = sp[tid + 256];
    float4 c0 = cp[tid];
    float4 c1 = cp[tid + 256];

    float mn = fminf(fminf(fminf(v0.x, v0.y), fminf(v0.z, v0.w)),
                     fminf(fminf(v1.x, v1.y), fminf(v1.z, v1.w)));
    mn = block_red(mn, 0, sred, tid);
    const float mval = mn - 1.f;

    v0.x = (c0.x == 0.f) ? mval : v0.x;
    v0.y = (c0.y == 0.f) ? mval : v0.y;
    v0.z = (c0.z == 0.f) ? mval : v0.z;
    v0.w = (c0.w == 0.f) ? mval : v0.w;
    v1.x = (c1.x == 0.f) ? mval : v1.x;
    v1.y = (c1.y == 0.f) ? mval : v1.y;
    v1.z = (c1.z == 0.f) ? mval : v1.z;
    v1.w = (c1.w == 0.f) ? mval : v1.w;

    float mx = fmaxf(fmaxf(fmaxf(v0.x, v0.y), fmaxf(v0.z, v0.w)),
                     fmaxf(fmaxf(v1.x, v1.y), fmaxf(v1.z, v1.w)));
    mx = block_red(mx, 1, sred, tid);

    float4 e0, e1;
    e0.x = expf(v0.x - mx); e0.y = expf(v0.y - mx);
    e0.z = expf(v0.z - mx); e0.w = expf(v0.w - mx);
    e1.x = expf(v1.x - mx); e1.y = expf(v1.y - mx);
    e1.z = expf(v1.z - mx); e1.w = expf(v1.w - mx);
    float sum = ((e0.x + e0.y) + (e0.z + e0.w)) + ((e1.x + e1.y) + (e1.z + e1.w));
    sum = block_red(sum, 2, sred, tid);
    const float inv = 1.f / sum;

    e0.x *= inv; e0.y *= inv; e0.z *= inv; e0.w *= inv;
    e1.x *= inv; e1.y *= inv; e1.z *= inv; e1.w *= inv;
    sp[tid]       = e0;
    sp[tid + 256] = e1;
}

// ===========================================================================
extern "C" void kernel_launch(void* const* d_in, const int* in_sizes, int n_in,
                              void* d_out, int out_size) {
    const float* X  = (const float*)d_in[0];   // (N, D) fp32
    const float* MU = (const float*)d_in[1];   // (C, D) fp32
    const float* cK = (const float*)d_in[2];   // (C,)   fp32
    float* out = (float*)d_out;                // (N, C) fp32

    cudaFuncSetAttribute(k_gemm_mma, cudaFuncAttributeMaxDynamicSharedMemorySize, SMEM_TOTAL);

    k_convX<<<(NROWS * DDIM) / 4 / 256, 256>>>(X);
    k_convMU<<<CCLS, 128>>>(MU);

    dim3 grid(CCLS / BN, NROWS / BM);          // (16, 256)
    k_gemm_mma<<<grid, 256, SMEM_TOTAL>>>(out);

    k_softmax<<<NROWS, 256>>>(out, cK);
}

// round 7
// speedup vs baseline: 2.6836x; 1.0010x over previous
#include <cuda_runtime.h>
#include <cuda_bf16.h>
#include <cstdint>

#define NROWS 32768
#define CCLS  2048
#define DDIM  512

// ---- GEMM tiling (mma.sync path, target-portable PTX) ----
#define BM 128
#define BN 128
#define BK 64                    // bf16 elems per chunk (128B per row)
#define KCHUNKS 24               // 3 products x (512/64)
#define TILE_BYTES 16384         // 128 rows x 128B
#define STAGE_BYTES (2 * TILE_BYTES)
#define NSTAGES 3
#define SMEM_TOTAL  (NSTAGES * STAGE_BYTES)   // 98304

// ---- scratch (__device__ globals; no cudaMalloc allowed) ----
__device__ __nv_bfloat16 g_Ah[(size_t)NROWS * DDIM];
__device__ __nv_bfloat16 g_Al[(size_t)NROWS * DDIM];
__device__ __nv_bfloat16 g_Bh[(size_t)CCLS * DDIM];
__device__ __nv_bfloat16 g_Bl[(size_t)CCLS * DDIM];
__device__ float g_m2[CCLS];

// ===========================================================================
// PTX helpers (all supported on plain sm_103 target)
// ===========================================================================
__device__ __forceinline__ uint32_t smem_u32(const void* p) {
    uint32_t a;
    asm("{ .reg .u64 t; cvta.to.shared.u64 t, %1; cvt.u32.u64 %0, t; }" : "=r"(a) : "l"(p));
    return a;
}

__device__ __forceinline__ void cp16(uint32_t dst, const void* src) {
    asm volatile("cp.async.cg.shared.global.L2::128B [%0], [%1], 16;" :: "r"(dst), "l"(src));
}
#define CP_COMMIT() asm volatile("cp.async.commit_group;" ::: "memory")
#define CP_WAIT1()  asm volatile("cp.async.wait_group 1;" ::: "memory")

__device__ __forceinline__ void ldsm4(uint32_t* r, uint32_t addr) {
    asm volatile("ldmatrix.sync.aligned.m8n8.x4.shared.b16 {%0,%1,%2,%3}, [%4];"
                 : "=r"(r[0]), "=r"(r[1]), "=r"(r[2]), "=r"(r[3]) : "r"(addr));
}

__device__ __forceinline__ void mma16816(float* d, const uint32_t* a, const uint32_t* b) {
    asm volatile("mma.sync.aligned.m16n8k16.row.col.f32.bf16.bf16.f32 "
                 "{%0,%1,%2,%3}, {%4,%5,%6,%7}, {%8,%9}, {%0,%1,%2,%3};"
                 : "+f"(d[0]), "+f"(d[1]), "+f"(d[2]), "+f"(d[3])
                 : "r"(a[0]), "r"(a[1]), "r"(a[2]), "r"(a[3]), "r"(b[0]), "r"(b[1]));
}

// ===========================================================================
// Kernel: convert X -> bf16 hi/lo
// ===========================================================================
__global__ __launch_bounds__(256) void k_convX(const float* __restrict__ X) {
    const int idx = blockIdx.x * 256 + threadIdx.x;        // float4 index
    float4 v = ((const float4*)X)[idx];
    __nv_bfloat16 h0 = __float2bfloat16(v.x), h1 = __float2bfloat16(v.y);
    __nv_bfloat16 h2 = __float2bfloat16(v.z), h3 = __float2bfloat16(v.w);
    __nv_bfloat16 l0 = __float2bfloat16(v.x - __bfloat162float(h0));
    __nv_bfloat16 l1 = __float2bfloat16(v.y - __bfloat162float(h1));
    __nv_bfloat16 l2 = __float2bfloat16(v.z - __bfloat162float(h2));
    __nv_bfloat16 l3 = __float2bfloat16(v.w - __bfloat162float(h3));
    __nv_bfloat162* Ah = (__nv_bfloat162*)g_Ah;
    __nv_bfloat162* Al = (__nv_bfloat162*)g_Al;
    __nv_bfloat162 p;
    p.x = h0; p.y = h1; Ah[idx * 2]     = p;
    p.x = h2; p.y = h3; Ah[idx * 2 + 1] = p;
    p.x = l0; p.y = l1; Al[idx * 2]     = p;
    p.x = l2; p.y = l3; Al[idx * 2 + 1] = p;
}

// ===========================================================================
// Kernel: convert MU -> bf16 hi/lo, fused with m2[c] = ||mu_c||^2
// ===========================================================================
__global__ __launch_bounds__(128) void k_convMU(const float* __restrict__ MU) {
    const int c = blockIdx.x;
    const size_t base = (size_t)c * DDIM;
    float s = 0.f;
    #pragma unroll
    for (int j = 0; j < 4; j++) {
        int d = threadIdx.x + j * 128;
        float x = MU[base + d];
        __nv_bfloat16 h = __float2bfloat16(x);
        __nv_bfloat16 l = __float2bfloat16(x - __bfloat162float(h));
        g_Bh[base + d] = h;
        g_Bl[base + d] = l;
        s = fmaf(x, x, s);
    }
    #pragma unroll
    for (int o = 16; o; o >>= 1) s += __shfl_xor_sync(0xffffffffu, s, o);
    __shared__ float sm[4];
    if ((threadIdx.x & 31) == 0) sm[threadIdx.x >> 5] = s;
    __syncthreads();
    if (threadIdx.x == 0) g_m2[c] = sm[0] + sm[1] + sm[2] + sm[3];
}

// ===========================================================================
// Kernel: HMMA GEMM  S[i][j] = 2*(x_i . mu_j) - m2[j]
// Virtual K = 1536: phase 0 = Ah.Bh, phase 1 = Al.Bh, phase 2 = Ah.Bl
// 3-stage cp.async pipeline; loads for chunk t+2 issued BEFORE compute of t.
// ===========================================================================
__device__ __forceinline__ void load_chunk(uint32_t stb, int t,
                                           int bm, int bn, int tid) {
    const int phase = t >> 3;
    const int koff  = (t & 7) * BK;
    const __nv_bfloat16* A = (phase == 1) ? g_Al : g_Ah;
    const __nv_bfloat16* B = (phase == 2) ? g_Bl : g_Bh;
    const uint32_t bs = stb + TILE_BYTES;
    #pragma unroll
    for (int i = 0; i < 4; i++) {
        int q = tid + i * 256;
        int r = q >> 3, c = q & 7;
        uint32_t off = r * 128 + ((c * 16) ^ ((r & 7) << 4));
        cp16(stb + off, A + (size_t)(bm + r) * DDIM + koff + c * 8);
    }
    #pragma unroll
    for (int i = 0; i < 4; i++) {
        int q = tid + i * 256;
        int r = q >> 3, c = q & 7;
        uint32_t off = r * 128 + ((c * 16) ^ ((r & 7) << 4));
        cp16(bs + off, B + (size_t)(bn + r) * DDIM + koff + c * 8);
    }
}

__global__ __launch_bounds__(256, 2) void k_gemm_mma(float* __restrict__ S) {
    extern __shared__ char smem[];
    const uint32_t sb = smem_u32(smem);
    const int tid = threadIdx.x;
    const int wid = tid >> 5, l = tid & 31;
    const int bm = blockIdx.y * BM, bn = blockIdx.x * BN;
    const int wm = (wid & 1) * 64;      // warp row offset (64 rows)
    const int wn = (wid >> 1) * 32;     // warp col offset (32 cols)

    float acc[4][4][4];                 // [m-tile][n-tile][frag]
    #pragma unroll
    for (int i = 0; i < 4; i++)
        #pragma unroll
        for (int j = 0; j < 4; j++)
            #pragma unroll
            for (int k = 0; k < 4; k++) acc[i][j][k] = 0.f;

    // per-lane ldmatrix addressing (swizzle nibble depends only on lane)
    const uint32_t sw   = (uint32_t)(l & 7) << 4;
    const int rowA = wm + (l & 15);                       // + mt*16
    const uint32_t aColSel = ((uint32_t)(l >> 4)) << 4;   // 0 / 16 bytes
    const int rowB = wn + ((l >> 4) << 3) + (l & 7);      // + bt*16
    const uint32_t bColSel = ((uint32_t)((l >> 3) & 1)) << 4;

    // prologue: chunks 0,1 -> stages 0,1
    load_chunk(sb + 0 * STAGE_BYTES, 0, bm, bn, tid); CP_COMMIT();
    load_chunk(sb + 1 * STAGE_BYTES, 1, bm, bn, tid); CP_COMMIT();

    int rs = 0;                         // read stage  (t % 3)
    int ws = 2;                         // write stage ((t+2) % 3)
    for (int t = 0; t < KCHUNKS; t++) {
        CP_WAIT1();                     // chunk t resident (<=1 group pending)
        __syncthreads();                // all warps past iteration t-1's reads of stage ws

        // issue loads for chunk t+2 FIRST: ~1.5 compute-spans of latency cover
        if (t + 2 < KCHUNKS) load_chunk(sb + ws * STAGE_BYTES, t + 2, bm, bn, tid);
        CP_COMMIT();                    // one group per iteration (possibly empty)

        const uint32_t as = sb + rs * STAGE_BYTES;
        const uint32_t bs = as + TILE_BYTES;

        #pragma unroll
        for (int ks = 0; ks < 4; ks++) {
            const uint32_t kb = (uint32_t)ks * 32;
            uint32_t a[4][4], b[2][4];
            #pragma unroll
            for (int bt = 0; bt < 2; bt++)
                ldsm4(b[bt], bs + (uint32_t)(rowB + bt * 16) * 128 + ((kb + bColSel) ^ sw));
            #pragma unroll
            for (int mt = 0; mt < 4; mt++)
                ldsm4(a[mt], as + (uint32_t)(rowA + mt * 16) * 128 + ((kb + aColSel) ^ sw));
            #pragma unroll
            for (int mt = 0; mt < 4; mt++) {
                mma16816(acc[mt][0], a[mt], &b[0][0]);
                mma16816(acc[mt][1], a[mt], &b[0][2]);
                mma16816(acc[mt][2], a[mt], &b[1][0]);
                mma16816(acc[mt][3], a[mt], &b[1][2]);
            }
        }

        rs = (rs == 2) ? 0 : rs + 1;
        ws = (ws == 2) ? 0 : ws + 1;
    }

    // epilogue: d -> 2*d - m2[col]
    const int cbase = bn + wn + (l & 3) * 2;
    float m2v[4][2];
    #pragma unroll
    for (int nt = 0; nt < 4; nt++) {
        m2v[nt][0] = g_m2[cbase + nt * 8];
        m2v[nt][1] = g_m2[cbase + nt * 8 + 1];
    }
    const int rbase = bm + wm + (l >> 2);
    #pragma unroll
    for (int mt = 0; mt < 4; mt++) {
        #pragma unroll
        for (int nt = 0; nt < 4; nt++) {
            float2 v0, v1;
            v0.x = 2.f * acc[mt][nt][0] - m2v[nt][0];
            v0.y = 2.f * acc[mt][nt][1] - m2v[nt][1];
            v1.x = 2.f * acc[mt][nt][2] - m2v[nt][0];
            v1.y = 2.f * acc[mt][nt][3] - m2v[nt][1];
            const int r = rbase + mt * 16;
            const int c = cbase + nt * 8;
            *(float2*)(S + (size_t)r * CCLS + c)       = v0;
            *(float2*)(S + (size_t)(r + 8) * CCLS + c) = v1;
        }
    }
}

// ===========================================================================
// Kernel: per-row masked softmax, in place on S
// ===========================================================================
__device__ __forceinline__ float block_red(float v, int mode, float* sred, int tid) {
    #pragma unroll
    for (int o = 16; o; o >>= 1) {
        float t = __shfl_xor_sync(0xffffffffu, v, o);
        v = (mode == 0) ? fminf(v, t) : (mode == 1) ? fmaxf(v, t) : (v + t);
    }
    __syncthreads();
    if ((tid & 31) == 0) sred[tid >> 5] = v;
    __syncthreads();
    float r;
    if (mode == 0) {
        r = fminf(fminf(fminf(sred[0], sred[1]), fminf(sred[2], sred[3])),
                  fminf(fminf(sred[4], sred[5]), fminf(sred[6], sred[7])));
    } else if (mode == 1) {
        r = fmaxf(fmaxf(fmaxf(sred[0], sred[1]), fmaxf(sred[2], sred[3])),
                  fmaxf(fmaxf(sred[4], sred[5]), fmaxf(sred[6], sred[7])));
    } else {
        r = ((sred[0] + sred[1]) + (sred[2] + sred[3])) +
            ((sred[4] + sred[5]) + (sred[6] + sred[7]));
    }
    return r;
}

__global__ __launch_bounds__(256) void k_softmax(float* __restrict__ S,
                                                 const float* __restrict__ cK) {
    __shared__ float sred[8];
    const int row = blockIdx.x;
    const int tid = threadIdx.x;
    float4* sp = (float4*)(S + (size_t)row * CCLS);
    const float4* cp = (const float4*)cK;

    float4 v0 = sp[tid];
    float4 v1 = sp[tid + 256];
    float4 c0 = cp[tid];
    float4 c1 = cp[tid + 256];

    float mn = fminf(fminf(fminf(v0.x, v0.y), fminf(v0.z, v0.w)),
                     fminf(fminf(v1.x, v1.y), fminf(v1.z, v1.w)));
    mn = block_red(mn, 0, sred, tid);
    const float mval = mn - 1.f;

    v0.x = (c0.x == 0.f) ? mval : v0.x;
    v0.y = (c0.y == 0.f) ? mval : v0.y;
    v0.z = (c0.z == 0.f) ? mval : v0.z;
    v0.w = (c0.w == 0.f) ? mval : v0.w;
    v1.x = (c1.x == 0.f) ? mval : v1.x;
    v1.y = (c1.y == 0.f) ? mval : v1.y;
    v1.z = (c1.z == 0.f) ? mval : v1.z;
    v1.w = (c1.w == 0.f) ? mval : v1.w;

    float mx = fmaxf(fmaxf(fmaxf(v0.x, v0.y), fmaxf(v0.z, v0.w)),
                     fmaxf(fmaxf(v1.x, v1.y), fmaxf(v1.z, v1.w)));
    mx = block_red(mx, 1, sred, tid);

    float4 e0, e1;
    e0.x = __expf(v0.x - mx); e0.y = __expf(v0.y - mx);
    e0.z = __expf(v0.z - mx); e0.w = __expf(v0.w - mx);
    e1.x = __expf(v1.x - mx); e1.y = __expf(v1.y - mx);
    e1.z = __expf(v1.z - mx); e1.w = __expf(v1.w - mx);
    float sum = ((e0.x + e0.y) + (e0.z + e0.w)) + ((e1.x + e1.y) + (e1.z + e1.w));
    sum = block_red(sum, 2, sred, tid);
    const float inv = 1.f / sum;

    e0.x *= inv; e0.y *= inv; e0.z *= inv; e0.w *= inv;
    e1.x *= inv; e1.y *= inv; e1.z *= inv; e1.w *= inv;
    sp[tid]       = e0;
    sp[tid + 256] = e1;
}

// ===========================================================================
extern "C" void kernel_launch(void* const* d_in, const int* in_sizes, int n_in,
                              void* d_out, int out_size) {
    const float* X  = (const float*)d_in[0];   // (N, D) fp32
    const float* MU = (const float*)d_in[1];   // (C, D) fp32
    const float* cK = (const float*)d_in[2];   // (C,)   fp32
    float* out = (float*)d_out;                // (N, C) fp32

    cudaFuncSetAttribute(k_gemm_mma, cudaFuncAttributeMaxDynamicSharedMemorySize, SMEM_TOTAL);

    k_convX<<<(NROWS * DDIM) / 4 / 256, 256>>>(X);
    k_convMU<<<CCLS, 128>>>(MU);

    dim3 grid(CCLS / BN, NROWS / BM);          // (16, 256)
    k_gemm_mma<<<grid, 256, SMEM_TOTAL>>>(out);

    k_softmax<<<NROWS, 256>>>(out, cK);
}